// round 3
// baseline (speedup 1.0000x reference)
#include <cuda_runtime.h>
#include <cuda_bf16.h>
#include <math.h>

#define B_   2
#define T_   2048
#define C_   1024
#define H_   16
#define DK_  64
#define HD_  1024   // H_*DK_
#define M_   4096   // B_*T_

// ---------------- scratch (no allocation allowed) ----------------
__device__ float g_q[(size_t)B_*H_*T_*DK_];
__device__ float g_k[(size_t)B_*H_*T_*DK_];
__device__ float g_v[(size_t)B_*H_*T_*DK_];
__device__ float g_o[(size_t)B_*T_*HD_];

// ---------------- SGEMM: C[M,N] = A[M,K] * B[K,N] ----------------
// BM=128, BN=128, BK=16, 8x8/thread, 256 threads, double-buffered smem.
#define BM 128
#define BN 128
#define BK 16
#define ASTR (BM + 4)

__global__ __launch_bounds__(256, 2)
void sgemm_kernel(const float* __restrict__ A,
                  const float* __restrict__ Bm,
                  float* __restrict__ Cout,
                  int M, int N, int K, int scatter)
{
    __shared__ float As[2][BK][ASTR];
    __shared__ float Bs[2][BK][BN];

    const int tid  = threadIdx.x;
    const int bRow = blockIdx.y;
    const int bCol = blockIdx.x;

    const float* Ab = A  + (size_t)bRow * BM * K;
    const float* Bb = Bm + (size_t)bCol * BN;

    const int tRow = tid >> 4;     // 0..15
    const int tCol = tid & 15;     // 0..15

    float acc[8][8];
#pragma unroll
    for (int i = 0; i < 8; i++)
#pragma unroll
        for (int j = 0; j < 8; j++) acc[i][j] = 0.0f;

    // preload tile 0 into buffer 0
#pragma unroll
    for (int l = 0; l < 2; l++) {
        int idx = l * 256 + tid;
        int r = idx >> 2, c = (idx & 3) * 4;
        float4 av = *(const float4*)(Ab + (size_t)r * K + c);
        As[0][c + 0][r] = av.x;
        As[0][c + 1][r] = av.y;
        As[0][c + 2][r] = av.z;
        As[0][c + 3][r] = av.w;
        int r2 = idx >> 5, c2 = (idx & 31) * 4;
        *(float4*)&Bs[0][r2][c2] = *(const float4*)(Bb + (size_t)r2 * N + c2);
    }
    __syncthreads();

    const int NT = K / BK;
    for (int kt = 0; kt < NT; kt++) {
        const int buf = kt & 1;

        float4 pa[2], pb[2];
        if (kt + 1 < NT) {
            const int k0 = (kt + 1) * BK;
#pragma unroll
            for (int l = 0; l < 2; l++) {
                int idx = l * 256 + tid;
                int r = idx >> 2, c = (idx & 3) * 4;
                pa[l] = *(const float4*)(Ab + (size_t)r * K + k0 + c);
                int r2 = idx >> 5, c2 = (idx & 31) * 4;
                pb[l] = *(const float4*)(Bb + (size_t)(k0 + r2) * N + c2);
            }
        }

#pragma unroll
        for (int d = 0; d < BK; d++) {
            float4 m0 = *(const float4*)&As[buf][d][tRow * 8];
            float4 m1 = *(const float4*)&As[buf][d][tRow * 8 + 4];
            float4 n0 = *(const float4*)&Bs[buf][d][tCol * 8];
            float4 n1 = *(const float4*)&Bs[buf][d][tCol * 8 + 4];
            float rm[8] = {m0.x, m0.y, m0.z, m0.w, m1.x, m1.y, m1.z, m1.w};
            float rn[8] = {n0.x, n0.y, n0.z, n0.w, n1.x, n1.y, n1.z, n1.w};
#pragma unroll
            for (int i = 0; i < 8; i++)
#pragma unroll
                for (int j = 0; j < 8; j++)
                    acc[i][j] = fmaf(rm[i], rn[j], acc[i][j]);
        }

        if (kt + 1 < NT) {
            const int nb = buf ^ 1;
#pragma unroll
            for (int l = 0; l < 2; l++) {
                int idx = l * 256 + tid;
                int r = idx >> 2, c = (idx & 3) * 4;
                As[nb][c + 0][r] = pa[l].x;
                As[nb][c + 1][r] = pa[l].y;
                As[nb][c + 2][r] = pa[l].z;
                As[nb][c + 3][r] = pa[l].w;
                int r2 = idx >> 5, c2 = (idx & 31) * 4;
                *(float4*)&Bs[nb][r2][c2] = pb[l];
            }
        }
        __syncthreads();
    }

    // epilogue
#pragma unroll
    for (int i = 0; i < 8; i++) {
        int row = bRow * BM + tRow * 8 + i;
#pragma unroll
        for (int j = 0; j < 8; j += 4) {
            int col = bCol * BN + tCol * 8 + j;
            float4 v = make_float4(acc[i][j], acc[i][j+1], acc[i][j+2], acc[i][j+3]);
            if (scatter) {
                int b = row / T_, t = row % T_;
                int h = col / DK_, d = col % DK_;
                *(float4*)(Cout + (((size_t)(b * H_ + h) * T_ + t) * DK_ + d)) = v;
            } else {
                *(float4*)(Cout + (size_t)row * N + col) = v;
            }
        }
    }
}

// ---------------- flash attention fp32 (causal, scale folded into Q) ------
// 128 query rows x 128 key cols per S-tile, 256 threads.
// S phase: 8x8 per thread (16x16 thread grid).
// PV/O phase: 8 rows x 4 d-cols per thread (DK=64 total).
// Q/K smem XOR-swizzled: offset d ^ ((row>>3 & 7) * 4) -> 8 distinct bank
// groups mod 32, conflict-free float4 reads across tx lanes.
#define FR 128
#define FC 128

__global__ __launch_bounds__(256, 1)
void flash_kernel(const float* __restrict__ q,
                  const float* __restrict__ k,
                  const float* __restrict__ v,
                  float* __restrict__ o)
{
    extern __shared__ float sm[];
    float* Qs = sm;                 // [128][64] swizzled
    float* Ks = Qs + FR * DK_;      // [128][64] swizzled
    float* Vs = Ks + FC * DK_;      // [128][64] row-major
    float* Ps = Vs + FC * DK_;      // [128][128]

    const int qt = (gridDim.x - 1) - blockIdx.x;  // heavy blocks first
    const int bh = blockIdx.y;
    const int b  = bh / H_;
    const int h  = bh % H_;

    const float* qb = q + (size_t)bh * T_ * DK_;
    const float* kb = k + (size_t)bh * T_ * DK_;
    const float* vb = v + (size_t)bh * T_ * DK_;

    const int tid = threadIdx.x;
    const int ty  = tid >> 4;       // 0..15 -> rows ty*8..+7
    const int tx  = tid & 15;       // 0..15 -> S cols tx*8..+7 ; O cols tx*4..+3
    const int i0  = qt * FR;

    const int qoff = (ty & 7) * 4;  // swizzle const for rows ty*8+i (i<8)
    const int koff = (tx & 7) * 4;  // swizzle const for rows tx*8+j (j<8)

    // load Q tile, pre-scaled by sqrt(dk)=8 (reference multiplies)
#pragma unroll
    for (int l = 0; l < 8; l++) {
        int idx = l * 256 + tid;
        int r = idx >> 4;           // 0..127
        int d = (idx & 15) * 4;
        float4 t4 = *(const float4*)(qb + (size_t)(i0 + r) * DK_ + d);
        *(float4*)&Qs[r * 64 + (d ^ (((r >> 3) & 7) * 4))] =
            make_float4(t4.x * 8.0f, t4.y * 8.0f, t4.z * 8.0f, t4.w * 8.0f);
    }

    float m_i[8], l_i[8], o_acc[8][4];
#pragma unroll
    for (int i = 0; i < 8; i++) {
        m_i[i] = -1e30f;
        l_i[i] = 0.0f;
#pragma unroll
        for (int j = 0; j < 4; j++) o_acc[i][j] = 0.0f;
    }

    for (int jt = 0; jt <= qt; jt++) {
        const int j0 = jt * FC;
        // load K (swizzled), V (row-major)
#pragma unroll
        for (int l = 0; l < 8; l++) {
            int idx = l * 256 + tid;
            int r = idx >> 4;
            int d = (idx & 15) * 4;
            *(float4*)&Ks[r * 64 + (d ^ (((r >> 3) & 7) * 4))] =
                *(const float4*)(kb + (size_t)(j0 + r) * DK_ + d);
            *(float4*)&Vs[r * 64 + d] =
                *(const float4*)(vb + (size_t)(j0 + r) * DK_ + d);
        }
        __syncthreads();

        // S = Q K^T  (8x8 per thread)
        float s[8][8];
#pragma unroll
        for (int i = 0; i < 8; i++)
#pragma unroll
            for (int j = 0; j < 8; j++) s[i][j] = 0.0f;

#pragma unroll 4
        for (int d = 0; d < DK_; d += 4) {
            float4 qv[8];
#pragma unroll
            for (int i = 0; i < 8; i++)
                qv[i] = *(const float4*)&Qs[(ty * 8 + i) * 64 + (d ^ qoff)];
#pragma unroll
            for (int j = 0; j < 8; j++) {
                float4 kv = *(const float4*)&Ks[(tx * 8 + j) * 64 + (d ^ koff)];
#pragma unroll
                for (int i = 0; i < 8; i++) {
                    s[i][j] = fmaf(qv[i].x, kv.x, s[i][j]);
                    s[i][j] = fmaf(qv[i].y, kv.y, s[i][j]);
                    s[i][j] = fmaf(qv[i].z, kv.z, s[i][j]);
                    s[i][j] = fmaf(qv[i].w, kv.w, s[i][j]);
                }
            }
        }

        // causal mask (diag tile only; i0 == j0 there)
        if (jt == qt) {
#pragma unroll
            for (int i = 0; i < 8; i++)
#pragma unroll
                for (int j = 0; j < 8; j++)
                    if (tx * 8 + j > ty * 8 + i) s[i][j] = -1e30f;
        }

        // online softmax per row (16-lane groups share a row set)
#pragma unroll
        for (int i = 0; i < 8; i++) {
            float mn = s[i][0];
#pragma unroll
            for (int j = 1; j < 8; j++) mn = fmaxf(mn, s[i][j]);
#pragma unroll
            for (int off = 8; off >= 1; off >>= 1)
                mn = fmaxf(mn, __shfl_xor_sync(0xffffffffu, mn, off, 16));

            float mnew = fmaxf(m_i[i], mn);
            float corr = __expf(m_i[i] - mnew);
            m_i[i] = mnew;

            float pj[8];
            float rs = 0.0f;
#pragma unroll
            for (int j = 0; j < 8; j++) {
                pj[j] = __expf(s[i][j] - mnew);
                rs += pj[j];
            }
            *(float4*)&Ps[(ty * 8 + i) * FC + tx * 8]     = make_float4(pj[0], pj[1], pj[2], pj[3]);
            *(float4*)&Ps[(ty * 8 + i) * FC + tx * 8 + 4] = make_float4(pj[4], pj[5], pj[6], pj[7]);
#pragma unroll
            for (int off = 8; off >= 1; off >>= 1)
                rs += __shfl_xor_sync(0xffffffffu, rs, off, 16);

            l_i[i] = l_i[i] * corr + rs;
#pragma unroll
            for (int j = 0; j < 4; j++) o_acc[i][j] *= corr;
        }
        // P producers/consumers for a given row set are the same 16-lane group
        __syncwarp();

        // O += P * V : thread owns rows ty*8.., d-cols tx*4..+3.
        // P read as float4 along kk for LDS efficiency.
#pragma unroll 2
        for (int kk = 0; kk < FC; kk += 4) {
            float4 v0 = *(const float4*)&Vs[(kk + 0) * 64 + tx * 4];
            float4 v1 = *(const float4*)&Vs[(kk + 1) * 64 + tx * 4];
            float4 v2 = *(const float4*)&Vs[(kk + 2) * 64 + tx * 4];
            float4 v3 = *(const float4*)&Vs[(kk + 3) * 64 + tx * 4];
#pragma unroll
            for (int i = 0; i < 8; i++) {
                float4 p4 = *(const float4*)&Ps[(ty * 8 + i) * FC + kk];
                o_acc[i][0] = fmaf(p4.x, v0.x, o_acc[i][0]);
                o_acc[i][1] = fmaf(p4.x, v0.y, o_acc[i][1]);
                o_acc[i][2] = fmaf(p4.x, v0.z, o_acc[i][2]);
                o_acc[i][3] = fmaf(p4.x, v0.w, o_acc[i][3]);
                o_acc[i][0] = fmaf(p4.y, v1.x, o_acc[i][0]);
                o_acc[i][1] = fmaf(p4.y, v1.y, o_acc[i][1]);
                o_acc[i][2] = fmaf(p4.y, v1.z, o_acc[i][2]);
                o_acc[i][3] = fmaf(p4.y, v1.w, o_acc[i][3]);
                o_acc[i][0] = fmaf(p4.z, v2.x, o_acc[i][0]);
                o_acc[i][1] = fmaf(p4.z, v2.y, o_acc[i][1]);
                o_acc[i][2] = fmaf(p4.z, v2.z, o_acc[i][2]);
                o_acc[i][3] = fmaf(p4.z, v2.w, o_acc[i][3]);
                o_acc[i][0] = fmaf(p4.w, v3.x, o_acc[i][0]);
                o_acc[i][1] = fmaf(p4.w, v3.y, o_acc[i][1]);
                o_acc[i][2] = fmaf(p4.w, v3.z, o_acc[i][2]);
                o_acc[i][3] = fmaf(p4.w, v3.w, o_acc[i][3]);
            }
        }
        __syncthreads();
    }

    // write O in [B, T, H*DK] layout: thread covers d-cols tx*4..+3
#pragma unroll
    for (int i = 0; i < 8; i++) {
        float inv = 1.0f / l_i[i];
        int t = i0 + ty * 8 + i;
        float* dst = o + (size_t)(b * T_ + t) * HD_ + h * DK_ + tx * 4;
        *(float4*)dst = make_float4(o_acc[i][0] * inv, o_acc[i][1] * inv,
                                    o_acc[i][2] * inv, o_acc[i][3] * inv);
    }
}

// ---------------- launch ----------------
extern "C" void kernel_launch(void* const* d_in, const int* in_sizes, int n_in,
                              void* d_out, int out_size)
{
    const float* x  = (const float*)d_in[0];
    const float* qm = (const float*)d_in[1];
    const float* km = (const float*)d_in[2];
    const float* vm = (const float*)d_in[3];
    const float* wm = (const float*)d_in[4];
    float* out = (float*)d_out;

    float *pq, *pk, *pv, *po;
    cudaGetSymbolAddress((void**)&pq, g_q);
    cudaGetSymbolAddress((void**)&pk, g_k);
    cudaGetSymbolAddress((void**)&pv, g_v);
    cudaGetSymbolAddress((void**)&po, g_o);

    const int smem = (3 * FR * DK_ + FR * FC) * (int)sizeof(float);  // 160KB
    cudaFuncSetAttribute(flash_kernel, cudaFuncAttributeMaxDynamicSharedMemorySize, smem);

    dim3 gemmGrid(HD_ / BN, M_ / BM);   // (8, 32)

    // QKV projections with scatter to [B,H,T,DK]
    sgemm_kernel<<<gemmGrid, 256>>>(x, qm, pq, M_, HD_, C_, 1);
    sgemm_kernel<<<gemmGrid, 256>>>(x, km, pk, M_, HD_, C_, 1);
    sgemm_kernel<<<gemmGrid, 256>>>(x, vm, pv, M_, HD_, C_, 1);

    // fused causal attention -> [B,T,H*DK]
    dim3 flashGrid(T_ / FR, B_ * H_);   // (16, 32)
    flash_kernel<<<flashGrid, 256, smem>>>(pq, pk, pv, po);

    // output projection
    sgemm_kernel<<<gemmGrid, 256>>>(po, wm, out, M_, HD_, C_, 0);
}

// round 5
// speedup vs baseline: 1.5812x; 1.5812x over previous
#include <cuda_runtime.h>
#include <cuda_bf16.h>
#include <math.h>

#define B_   2
#define T_   2048
#define C_   1024
#define H_   16
#define DK_  64
#define HD_  1024   // H_*DK_
#define M_   4096   // B_*T_

// ---------------- scratch (no allocation allowed) ----------------
__device__ float g_q[(size_t)B_*H_*T_*DK_];
__device__ float g_k[(size_t)B_*H_*T_*DK_];
__device__ float g_v[(size_t)B_*H_*T_*DK_];
__device__ float g_o[(size_t)B_*T_*HD_];

// ---------------- SGEMM (round-1 proven config) ----------------
// BM=128, BN=128, BK=16, 8x8/thread, 256 threads, single-buffered.
// blockIdx.z selects (B, C) pair -> fused QKV in one launch.
#define BM 128
#define BN 128
#define BK 16

__global__ __launch_bounds__(256, 2)
void sgemm_kernel(const float* __restrict__ A,
                  const float* __restrict__ B0,
                  const float* __restrict__ B1,
                  const float* __restrict__ B2,
                  float* __restrict__ C0,
                  float* __restrict__ C1,
                  float* __restrict__ C2,
                  int M, int N, int K, int scatter)
{
    __shared__ float As[BK][BM];
    __shared__ float Bs[BK][BN];

    const int tid  = threadIdx.x;
    const int bRow = blockIdx.y;
    const int bCol = blockIdx.x;
    const int z    = blockIdx.z;

    const float* Bm   = (z == 0) ? B0 : (z == 1) ? B1 : B2;
    float*       Cout = (z == 0) ? C0 : (z == 1) ? C1 : C2;

    const float* Ab = A  + (size_t)bRow * BM * K;
    const float* Bb = Bm + (size_t)bCol * BN;

    const int tRow = tid >> 4;     // 0..15
    const int tCol = tid & 15;     // 0..15

    float acc[8][8];
#pragma unroll
    for (int i = 0; i < 8; i++)
#pragma unroll
        for (int j = 0; j < 8; j++) acc[i][j] = 0.0f;

    float regM[8], regN[8];

    for (int k0 = 0; k0 < K; k0 += BK) {
#pragma unroll
        for (int l = 0; l < 2; l++) {
            int idx = l * 256 + tid;
            int r = idx >> 2;              // 0..127
            int c = (idx & 3) * 4;         // 0,4,8,12
            float4 av = *(const float4*)(Ab + (size_t)r * K + k0 + c);
            As[c + 0][r] = av.x;
            As[c + 1][r] = av.y;
            As[c + 2][r] = av.z;
            As[c + 3][r] = av.w;
        }
#pragma unroll
        for (int l = 0; l < 2; l++) {
            int idx = l * 256 + tid;
            int r = idx >> 5;              // 0..15
            int c = (idx & 31) * 4;        // 0..124
            *(float4*)(&Bs[r][c]) = *(const float4*)(Bb + (size_t)(k0 + r) * N + c);
        }
        __syncthreads();

#pragma unroll
        for (int d = 0; d < BK; d++) {
#pragma unroll
            for (int i = 0; i < 8; i++) regM[i] = As[d][tRow * 8 + i];
#pragma unroll
            for (int j = 0; j < 8; j++) regN[j] = Bs[d][tCol * 8 + j];
#pragma unroll
            for (int i = 0; i < 8; i++)
#pragma unroll
                for (int j = 0; j < 8; j++)
                    acc[i][j] = fmaf(regM[i], regN[j], acc[i][j]);
        }
        __syncthreads();
    }

    // epilogue
#pragma unroll
    for (int i = 0; i < 8; i++) {
        int row = bRow * BM + tRow * 8 + i;
#pragma unroll
        for (int j = 0; j < 8; j += 4) {
            int col = bCol * BN + tCol * 8 + j;
            float4 v = make_float4(acc[i][j], acc[i][j+1], acc[i][j+2], acc[i][j+3]);
            if (scatter) {
                int b = row / T_, t = row % T_;
                int h = col / DK_, d = col % DK_;
                *(float4*)(Cout + (((size_t)(b * H_ + h) * T_ + t) * DK_ + d)) = v;
            } else {
                *(float4*)(Cout + (size_t)row * N + col) = v;
            }
        }
    }
}

// ---------------- flash attention fp32, 512 threads ----------------
// 128 q-rows x 128 k-cols per S-tile. Warp w owns rows w*8..w*8+7.
// S phase: 8 rows x 4 cols per thread (cols lane*4..+3).
// PV phase: 8 rows x 2 d-cols per thread (cols lane*2..+1).
// Q/K smem swizzle: float4 at row*64 + (d ^ ((row>>2 & 7)*4)).
//   K reads: rows lane*4+j -> swizzle (lane&7)*4, distinct per phase-octet
//   lane -> conflict-free. Q/P reads are warp-uniform -> broadcast.
#define FR 128
#define FC 128

__global__ __launch_bounds__(512, 1)
void flash_kernel(const float* __restrict__ q,
                  const float* __restrict__ k,
                  const float* __restrict__ v,
                  float* __restrict__ o)
{
    extern __shared__ float sm[];
    float* Qs = sm;                 // [128][64] swizzled
    float* Ks = Qs + FR * DK_;      // [128][64] swizzled
    float* Vs = Ks + FC * DK_;      // [128][64] row-major
    float* Ps = Vs + FC * DK_;      // [128][128]

    const int qt = (gridDim.x - 1) - blockIdx.x;  // heavy tiles first
    const int bh = blockIdx.y;
    const int b  = bh / H_;
    const int h  = bh % H_;

    const float* qb = q + (size_t)bh * T_ * DK_;
    const float* kb = k + (size_t)bh * T_ * DK_;
    const float* vb = v + (size_t)bh * T_ * DK_;

    const int tid  = threadIdx.x;
    const int w    = tid >> 5;      // warp 0..15 -> rows w*8..+7
    const int lane = tid & 31;      // S cols lane*4..+3 ; O cols lane*2..+1
    const int i0   = qt * FR;

    const int ksw  = (lane & 7) * 4;            // swizzle for K rows lane*4+j
    const int qsw0 = ((w * 2) & 7) * 4;         // rows w*8 .. w*8+3
    const int qsw1 = ((w * 2 + 1) & 7) * 4;     // rows w*8+4 .. w*8+7

    // load Q tile, pre-scaled by sqrt(dk)=8 (reference multiplies)
#pragma unroll
    for (int l = 0; l < 4; l++) {
        int idx = l * 512 + tid;
        int r = idx >> 4;           // 0..127
        int d = (idx & 15) * 4;
        float4 t4 = *(const float4*)(qb + (size_t)(i0 + r) * DK_ + d);
        *(float4*)&Qs[r * 64 + (d ^ (((r >> 2) & 7) * 4))] =
            make_float4(t4.x * 8.0f, t4.y * 8.0f, t4.z * 8.0f, t4.w * 8.0f);
    }

    float m_i[8], l_i[8], o_acc[8][2];
#pragma unroll
    for (int i = 0; i < 8; i++) {
        m_i[i] = -1e30f;
        l_i[i] = 0.0f;
        o_acc[i][0] = 0.0f;
        o_acc[i][1] = 0.0f;
    }

    for (int jt = 0; jt <= qt; jt++) {
        const int j0 = jt * FC;
        // load K (swizzled), V (row-major)
#pragma unroll
        for (int l = 0; l < 4; l++) {
            int idx = l * 512 + tid;
            int r = idx >> 4;
            int d = (idx & 15) * 4;
            *(float4*)&Ks[r * 64 + (d ^ (((r >> 2) & 7) * 4))] =
                *(const float4*)(kb + (size_t)(j0 + r) * DK_ + d);
            *(float4*)&Vs[r * 64 + d] =
                *(const float4*)(vb + (size_t)(j0 + r) * DK_ + d);
        }
        __syncthreads();

        // S = Q K^T : 8 rows x 4 cols per thread
        float s[8][4];
#pragma unroll
        for (int i = 0; i < 8; i++)
#pragma unroll
            for (int j = 0; j < 4; j++) s[i][j] = 0.0f;

#pragma unroll 4
        for (int d = 0; d < DK_; d += 4) {
            float4 kv[4];
#pragma unroll
            for (int j = 0; j < 4; j++)
                kv[j] = *(const float4*)&Ks[(lane * 4 + j) * 64 + (d ^ ksw)];
#pragma unroll
            for (int i = 0; i < 8; i++) {
                float4 qv = *(const float4*)&Qs[(w * 8 + i) * 64 +
                                                (d ^ (i < 4 ? qsw0 : qsw1))];
#pragma unroll
                for (int j = 0; j < 4; j++) {
                    s[i][j] = fmaf(qv.x, kv[j].x, s[i][j]);
                    s[i][j] = fmaf(qv.y, kv[j].y, s[i][j]);
                    s[i][j] = fmaf(qv.z, kv[j].z, s[i][j]);
                    s[i][j] = fmaf(qv.w, kv[j].w, s[i][j]);
                }
            }
        }

        // causal mask (diag tile only)
        if (jt == qt) {
#pragma unroll
            for (int i = 0; i < 8; i++)
#pragma unroll
                for (int j = 0; j < 4; j++)
                    if (lane * 4 + j > w * 8 + i) s[i][j] = -1e30f;
        }

        // online softmax per row; full-warp reductions
#pragma unroll
        for (int i = 0; i < 8; i++) {
            float mn = fmaxf(fmaxf(s[i][0], s[i][1]), fmaxf(s[i][2], s[i][3]));
#pragma unroll
            for (int off = 16; off >= 1; off >>= 1)
                mn = fmaxf(mn, __shfl_xor_sync(0xffffffffu, mn, off));

            float mnew = fmaxf(m_i[i], mn);
            float corr = __expf(m_i[i] - mnew);
            m_i[i] = mnew;

            float p0 = __expf(s[i][0] - mnew);
            float p1 = __expf(s[i][1] - mnew);
            float p2 = __expf(s[i][2] - mnew);
            float p3 = __expf(s[i][3] - mnew);
            *(float4*)&Ps[(w * 8 + i) * FC + lane * 4] = make_float4(p0, p1, p2, p3);

            float rs = p0 + p1 + p2 + p3;
#pragma unroll
            for (int off = 16; off >= 1; off >>= 1)
                rs += __shfl_xor_sync(0xffffffffu, rs, off);

            l_i[i] = l_i[i] * corr + rs;
            o_acc[i][0] *= corr;
            o_acc[i][1] *= corr;
        }
        // P rows w*8+i are produced and consumed by warp w only
        __syncwarp();

        // O += P * V : 8 rows x 2 d-cols (lane*2) per thread
#pragma unroll 4
        for (int kk = 0; kk < FC; kk += 4) {
            float2 v0 = *(const float2*)&Vs[(kk + 0) * 64 + lane * 2];
            float2 v1 = *(const float2*)&Vs[(kk + 1) * 64 + lane * 2];
            float2 v2 = *(const float2*)&Vs[(kk + 2) * 64 + lane * 2];
            float2 v3 = *(const float2*)&Vs[(kk + 3) * 64 + lane * 2];
#pragma unroll
            for (int i = 0; i < 8; i++) {
                float4 p4 = *(const float4*)&Ps[(w * 8 + i) * FC + kk];
                o_acc[i][0] = fmaf(p4.x, v0.x, o_acc[i][0]);
                o_acc[i][1] = fmaf(p4.x, v0.y, o_acc[i][1]);
                o_acc[i][0] = fmaf(p4.y, v1.x, o_acc[i][0]);
                o_acc[i][1] = fmaf(p4.y, v1.y, o_acc[i][1]);
                o_acc[i][0] = fmaf(p4.z, v2.x, o_acc[i][0]);
                o_acc[i][1] = fmaf(p4.z, v2.y, o_acc[i][1]);
                o_acc[i][0] = fmaf(p4.w, v3.x, o_acc[i][0]);
                o_acc[i][1] = fmaf(p4.w, v3.y, o_acc[i][1]);
            }
        }
        __syncthreads();
    }

    // write O in [B, T, H*DK] layout: thread covers d-cols lane*2..+1
#pragma unroll
    for (int i = 0; i < 8; i++) {
        float inv = 1.0f / l_i[i];
        int t = i0 + w * 8 + i;
        float* dst = o + (size_t)(b * T_ + t) * HD_ + h * DK_ + lane * 2;
        *(float2*)dst = make_float2(o_acc[i][0] * inv, o_acc[i][1] * inv);
    }
}

// ---------------- launch ----------------
extern "C" void kernel_launch(void* const* d_in, const int* in_sizes, int n_in,
                              void* d_out, int out_size)
{
    const float* x  = (const float*)d_in[0];
    const float* qm = (const float*)d_in[1];
    const float* km = (const float*)d_in[2];
    const float* vm = (const float*)d_in[3];
    const float* wm = (const float*)d_in[4];
    float* out = (float*)d_out;

    float *pq, *pk, *pv, *po;
    cudaGetSymbolAddress((void**)&pq, g_q);
    cudaGetSymbolAddress((void**)&pk, g_k);
    cudaGetSymbolAddress((void**)&pv, g_v);
    cudaGetSymbolAddress((void**)&po, g_o);

    const int smem = (3 * FR * DK_ + FR * FC) * (int)sizeof(float);  // 160KB
    cudaFuncSetAttribute(flash_kernel, cudaFuncAttributeMaxDynamicSharedMemorySize, smem);

    // fused QKV projection (scatter to [B,H,T,DK]), z picks weight/output
    dim3 qkvGrid(HD_ / BN, M_ / BM, 3);   // (8, 32, 3)
    sgemm_kernel<<<qkvGrid, 256>>>(x, qm, km, vm, pq, pk, pv, M_, HD_, C_, 1);

    // fused causal attention -> [B,T,H*DK]
    dim3 flashGrid(T_ / FR, B_ * H_);     // (16, 32)
    flash_kernel<<<flashGrid, 512, smem>>>(pq, pk, pv, po);

    // output projection
    dim3 oGrid(HD_ / BN, M_ / BM, 1);
    sgemm_kernel<<<oGrid, 256>>>(po, wm, wm, wm, out, out, out, M_, HD_, C_, 0);
}

// round 8
// speedup vs baseline: 2.2018x; 1.3925x over previous
#include <cuda_runtime.h>
#include <cuda_bf16.h>
#include <stdint.h>
#include <math.h>

#define B_   2
#define T_   2048
#define C_   1024
#define H_   16
#define DK_  64
#define HD_  1024   // H_*DK_
#define M_   4096   // B_*T_
#define KDIM 1024
#define NCH  16     // KDIM / 64

// ---------------- scratch (no allocation allowed) ----------------
__device__ float g_q[(size_t)B_*H_*T_*DK_];
__device__ float g_k[(size_t)B_*H_*T_*DK_];
__device__ float g_v[(size_t)B_*H_*T_*DK_];
__device__ float g_o[(size_t)B_*T_*HD_];

// ---------------- helpers ----------------
__device__ __forceinline__ uint32_t smem_u32(const void* p) {
    uint32_t a;
    asm("{ .reg .u64 t; cvta.to.shared.u64 t, %1; cvt.u32.u64 %0, t; }"
        : "=r"(a) : "l"(p));
    return a;
}
#define SW128(o) ((uint32_t)(o) ^ ((((uint32_t)(o)) >> 3) & 0x70u))

__device__ __forceinline__ void ldm_x4(uint32_t* r, uint32_t addr) {
    asm volatile("ldmatrix.sync.aligned.m8n8.x4.shared.b16 {%0,%1,%2,%3}, [%4];"
                 : "=r"(r[0]), "=r"(r[1]), "=r"(r[2]), "=r"(r[3]) : "r"(addr));
}

__device__ __forceinline__ void mma_bf16(float* c, const uint32_t* a,
                                         uint32_t b0, uint32_t b1) {
    asm volatile(
        "mma.sync.aligned.m16n8k16.row.col.f32.bf16.bf16.f32 "
        "{%0,%1,%2,%3}, {%4,%5,%6,%7}, {%8,%9}, {%0,%1,%2,%3};"
        : "+f"(c[0]), "+f"(c[1]), "+f"(c[2]), "+f"(c[3])
        : "r"(a[0]), "r"(a[1]), "r"(a[2]), "r"(a[3]), "r"(b0), "r"(b1));
}

// split fp32 pair into packed bf16-hi pair and bf16-lo pair
__device__ __forceinline__ void split2(float a, float b, uint32_t& hi, uint32_t& lo) {
    __nv_bfloat16 ah = __float2bfloat16(a);
    __nv_bfloat16 bh = __float2bfloat16(b);
    __nv_bfloat16 al = __float2bfloat16(a - __bfloat162float(ah));
    __nv_bfloat16 bl = __float2bfloat16(b - __bfloat162float(bh));
    uint16_t ahb = *(uint16_t*)&ah, bhb = *(uint16_t*)&bh;
    uint16_t alb = *(uint16_t*)&al, blb = *(uint16_t*)&bl;
    hi = (uint32_t)ahb | ((uint32_t)bhb << 16);
    lo = (uint32_t)alb | ((uint32_t)blb << 16);
}

// ---------------- bf16x3 mma.sync GEMM: C[4096,1024] = A * W --------------
// CTA tile 128x128, 512 threads, 16 warps (4x4), warp tile 32x32.
// K chunks of 64. Per chunk: convert A (fp32->bf16 hi/lo, swizzled [m][k]),
// stage W fp32 then transpose to [n][k] bf16 hi/lo. 3 passes of mma.sync:
// Ahi*Bhi + Ahi*Blo + Alo*Bhi.
// smem bytes: AHI 0, ALO 16384, BHI 32768, BLO 49152, STAGE(fp32 64x132) 65536
#define SM_AHI 0u
#define SM_ALO 16384u
#define SM_BHI 32768u
#define SM_BLO 49152u
#define SM_STG 65536u
#define SM_TOTAL (65536 + 64 * 132 * 4)   // 99328

__global__ void __launch_bounds__(512, 1)
gemm_mma_kernel(const float* __restrict__ A,
                const float* __restrict__ W0,
                const float* __restrict__ W1,
                const float* __restrict__ W2,
                float* __restrict__ C0,
                float* __restrict__ C1,
                float* __restrict__ C2,
                int scatter)
{
    extern __shared__ char gsm[];
    const uint32_t sb = smem_u32(gsm);
    float* stage = (float*)(gsm + SM_STG);

    const int tid  = threadIdx.x;
    const int wid  = tid >> 5;
    const int lane = tid & 31;
    const int bRow = blockIdx.y;
    const int bCol = blockIdx.x;
    const int z    = blockIdx.z;

    const float* W    = (z == 0) ? W0 : (z == 1) ? W1 : W2;
    float*       Cout = (z == 0) ? C0 : (z == 1) ? C1 : C2;

    const int wm = wid >> 2;          // 0..3
    const int wn = wid & 3;           // 0..3
    const int m0 = wm * 32;
    const int n0 = wn * 32;

    float acc[2][4][4];               // [mt][n8][reg]
#pragma unroll
    for (int mt = 0; mt < 2; mt++)
#pragma unroll
        for (int j = 0; j < 4; j++)
#pragma unroll
            for (int r = 0; r < 4; r++) acc[mt][j][r] = 0.0f;

    for (int ch = 0; ch < NCH; ch++) {
        if (ch) __syncthreads();      // prior mma phase done reading smem

        // ---- A tile: [128 m][64 k] fp32 -> bf16 hi/lo, swizzled ----
#pragma unroll
        for (int p = 0; p < 4; p++) {
            int idx = p * 512 + tid;
            int r = idx >> 4, c4 = idx & 15;
            float4 v = *(const float4*)(A + (size_t)(bRow * 128 + r) * KDIM
                                        + ch * 64 + c4 * 4);
            uint32_t h0, h1, l0, l1;
            split2(v.x, v.y, h0, l0);
            split2(v.z, v.w, h1, l1);
            uint32_t off = SW128(r * 128 + c4 * 8);
            *(uint2*)(gsm + SM_AHI + off) = make_uint2(h0, h1);
            *(uint2*)(gsm + SM_ALO + off) = make_uint2(l0, l1);
        }
        // ---- B stage 1: W chunk [64 k][128 n] fp32, coalesced ----
#pragma unroll
        for (int p = 0; p < 4; p++) {
            int idx = p * 512 + tid;
            int r = idx >> 5, c4 = idx & 31;
            *(float4*)(stage + r * 132 + c4 * 4) =
                *(const float4*)(W + (size_t)(ch * 64 + r) * HD_
                                 + bCol * 128 + c4 * 4);
        }
        __syncthreads();
        // ---- B stage 2: transpose -> [128 n][64 k] bf16 hi/lo, swizzled ---
        {
            int n  = tid & 127;
            int k0 = (tid >> 7) * 16;
#pragma unroll
            for (int half = 0; half < 2; half++) {
                uint32_t hh[4], ll[4];
#pragma unroll
                for (int j = 0; j < 4; j++) {
                    float f0 = stage[(k0 + half * 8 + 2 * j)     * 132 + n];
                    float f1 = stage[(k0 + half * 8 + 2 * j + 1) * 132 + n];
                    split2(f0, f1, hh[j], ll[j]);
                }
                uint32_t off = SW128(n * 128 + (k0 + half * 8) * 2);
                *(uint4*)(gsm + SM_BHI + off) = make_uint4(hh[0], hh[1], hh[2], hh[3]);
                *(uint4*)(gsm + SM_BLO + off) = make_uint4(ll[0], ll[1], ll[2], ll[3]);
            }
        }
        __syncthreads();

        // ---- MMA phase: 4 k16 steps ----
#pragma unroll
        for (int ks = 0; ks < 4; ks++) {
            const uint32_t colb = ks * 32 + (lane >> 4) * 16;  // byte col
            uint32_t ahi[2][4], alo[2][4], bhi[2][4], blo[2][4];
#pragma unroll
            for (int mt = 0; mt < 2; mt++) {
                uint32_t roff = (uint32_t)(m0 + mt * 16 + (lane & 15)) * 128 + colb;
                ldm_x4(ahi[mt], sb + SM_AHI + SW128(roff));
                ldm_x4(alo[mt], sb + SM_ALO + SW128(roff));
            }
#pragma unroll
            for (int nt = 0; nt < 2; nt++) {
                uint32_t roff = (uint32_t)(n0 + nt * 16 + (lane & 15)) * 128 + colb;
                ldm_x4(bhi[nt], sb + SM_BHI + SW128(roff));
                ldm_x4(blo[nt], sb + SM_BLO + SW128(roff));
            }
            // pass 1: Ahi * Bhi
#pragma unroll
            for (int mt = 0; mt < 2; mt++)
#pragma unroll
                for (int j = 0; j < 4; j++)
                    mma_bf16(acc[mt][j], ahi[mt], bhi[j >> 1][j & 1], bhi[j >> 1][(j & 1) + 2]);
            // pass 2: Ahi * Blo
#pragma unroll
            for (int mt = 0; mt < 2; mt++)
#pragma unroll
                for (int j = 0; j < 4; j++)
                    mma_bf16(acc[mt][j], ahi[mt], blo[j >> 1][j & 1], blo[j >> 1][(j & 1) + 2]);
            // pass 3: Alo * Bhi
#pragma unroll
            for (int mt = 0; mt < 2; mt++)
#pragma unroll
                for (int j = 0; j < 4; j++)
                    mma_bf16(acc[mt][j], alo[mt], bhi[j >> 1][j & 1], bhi[j >> 1][(j & 1) + 2]);
        }
    }

    // ---- epilogue: C fragment layout -> gmem float2 stores ----
#pragma unroll
    for (int mt = 0; mt < 2; mt++) {
#pragma unroll
        for (int j = 0; j < 4; j++) {
            int row = bRow * 128 + m0 + mt * 16 + (lane >> 2);
            int col = bCol * 128 + n0 + j * 8 + (lane & 3) * 2;
#pragma unroll
            for (int half = 0; half < 2; half++) {
                int rr = row + half * 8;
                float2 v = make_float2(acc[mt][j][half * 2], acc[mt][j][half * 2 + 1]);
                if (scatter) {
                    int b = rr >> 11, t = rr & 2047, h = col >> 6, d = col & 63;
                    *(float2*)(Cout + (((size_t)(b * H_ + h) * T_ + t) * DK_ + d)) = v;
                } else {
                    *(float2*)(Cout + (size_t)rr * HD_ + col) = v;
                }
            }
        }
    }
}

// ---------------- flash attention fp32, 512 threads (round-5 proven) -------
#define FR 128
#define FC 128

__global__ __launch_bounds__(512, 1)
void flash_kernel(const float* __restrict__ q,
                  const float* __restrict__ k,
                  const float* __restrict__ v,
                  float* __restrict__ o)
{
    extern __shared__ float fsm[];
    float* Qs = fsm;
    float* Ks = Qs + FR * DK_;
    float* Vs = Ks + FC * DK_;
    float* Ps = Vs + FC * DK_;

    const int qt = (gridDim.x - 1) - blockIdx.x;
    const int bh = blockIdx.y;
    const int b  = bh / H_;
    const int h  = bh % H_;

    const float* qb = q + (size_t)bh * T_ * DK_;
    const float* kb = k + (size_t)bh * T_ * DK_;
    const float* vb = v + (size_t)bh * T_ * DK_;

    const int tid  = threadIdx.x;
    const int w    = tid >> 5;
    const int lane = tid & 31;
    const int i0   = qt * FR;

    const int ksw  = (lane & 7) * 4;
    const int qsw0 = ((w * 2) & 7) * 4;
    const int qsw1 = ((w * 2 + 1) & 7) * 4;

#pragma unroll
    for (int l = 0; l < 4; l++) {
        int idx = l * 512 + tid;
        int r = idx >> 4;
        int d = (idx & 15) * 4;
        float4 t4 = *(const float4*)(qb + (size_t)(i0 + r) * DK_ + d);
        *(float4*)&Qs[r * 64 + (d ^ (((r >> 2) & 7) * 4))] =
            make_float4(t4.x * 8.0f, t4.y * 8.0f, t4.z * 8.0f, t4.w * 8.0f);
    }

    float m_i[8], l_i[8], o_acc[8][2];
#pragma unroll
    for (int i = 0; i < 8; i++) {
        m_i[i] = -1e30f;
        l_i[i] = 0.0f;
        o_acc[i][0] = 0.0f;
        o_acc[i][1] = 0.0f;
    }

    for (int jt = 0; jt <= qt; jt++) {
        const int j0 = jt * FC;
#pragma unroll
        for (int l = 0; l < 4; l++) {
            int idx = l * 512 + tid;
            int r = idx >> 4;
            int d = (idx & 15) * 4;
            *(float4*)&Ks[r * 64 + (d ^ (((r >> 2) & 7) * 4))] =
                *(const float4*)(kb + (size_t)(j0 + r) * DK_ + d);
            *(float4*)&Vs[r * 64 + d] =
                *(const float4*)(vb + (size_t)(j0 + r) * DK_ + d);
        }
        __syncthreads();

        float s[8][4];
#pragma unroll
        for (int i = 0; i < 8; i++)
#pragma unroll
            for (int j = 0; j < 4; j++) s[i][j] = 0.0f;

#pragma unroll 4
        for (int d = 0; d < DK_; d += 4) {
            float4 kv[4];
#pragma unroll
            for (int j = 0; j < 4; j++)
                kv[j] = *(const float4*)&Ks[(lane * 4 + j) * 64 + (d ^ ksw)];
#pragma unroll
            for (int i = 0; i < 8; i++) {
                float4 qv = *(const float4*)&Qs[(w * 8 + i) * 64 +
                                                (d ^ (i < 4 ? qsw0 : qsw1))];
#pragma unroll
                for (int j = 0; j < 4; j++) {
                    s[i][j] = fmaf(qv.x, kv[j].x, s[i][j]);
                    s[i][j] = fmaf(qv.y, kv[j].y, s[i][j]);
                    s[i][j] = fmaf(qv.z, kv[j].z, s[i][j]);
                    s[i][j] = fmaf(qv.w, kv[j].w, s[i][j]);
                }
            }
        }

        if (jt == qt) {
#pragma unroll
            for (int i = 0; i < 8; i++)
#pragma unroll
                for (int j = 0; j < 4; j++)
                    if (lane * 4 + j > w * 8 + i) s[i][j] = -1e30f;
        }

#pragma unroll
        for (int i = 0; i < 8; i++) {
            float mn = fmaxf(fmaxf(s[i][0], s[i][1]), fmaxf(s[i][2], s[i][3]));
#pragma unroll
            for (int off = 16; off >= 1; off >>= 1)
                mn = fmaxf(mn, __shfl_xor_sync(0xffffffffu, mn, off));

            float mnew = fmaxf(m_i[i], mn);
            float corr = __expf(m_i[i] - mnew);
            m_i[i] = mnew;

            float p0 = __expf(s[i][0] - mnew);
            float p1 = __expf(s[i][1] - mnew);
            float p2 = __expf(s[i][2] - mnew);
            float p3 = __expf(s[i][3] - mnew);
            *(float4*)&Ps[(w * 8 + i) * FC + lane * 4] = make_float4(p0, p1, p2, p3);

            float rs = p0 + p1 + p2 + p3;
#pragma unroll
            for (int off = 16; off >= 1; off >>= 1)
                rs += __shfl_xor_sync(0xffffffffu, rs, off);

            l_i[i] = l_i[i] * corr + rs;
            o_acc[i][0] *= corr;
            o_acc[i][1] *= corr;
        }
        __syncwarp();

#pragma unroll 4
        for (int kk = 0; kk < FC; kk += 4) {
            float2 v0 = *(const float2*)&Vs[(kk + 0) * 64 + lane * 2];
            float2 v1 = *(const float2*)&Vs[(kk + 1) * 64 + lane * 2];
            float2 v2 = *(const float2*)&Vs[(kk + 2) * 64 + lane * 2];
            float2 v3 = *(const float2*)&Vs[(kk + 3) * 64 + lane * 2];
#pragma unroll
            for (int i = 0; i < 8; i++) {
                float4 p4 = *(const float4*)&Ps[(w * 8 + i) * FC + kk];
                o_acc[i][0] = fmaf(p4.x, v0.x, o_acc[i][0]);
                o_acc[i][1] = fmaf(p4.x, v0.y, o_acc[i][1]);
                o_acc[i][0] = fmaf(p4.y, v1.x, o_acc[i][0]);
                o_acc[i][1] = fmaf(p4.y, v1.y, o_acc[i][1]);
                o_acc[i][0] = fmaf(p4.z, v2.x, o_acc[i][0]);
                o_acc[i][1] = fmaf(p4.z, v2.y, o_acc[i][1]);
                o_acc[i][0] = fmaf(p4.w, v3.x, o_acc[i][0]);
                o_acc[i][1] = fmaf(p4.w, v3.y, o_acc[i][1]);
            }
        }
        __syncthreads();
    }

#pragma unroll
    for (int i = 0; i < 8; i++) {
        float inv = 1.0f / l_i[i];
        int t = i0 + w * 8 + i;
        float* dst = o + (size_t)(b * T_ + t) * HD_ + h * DK_ + lane * 2;
        *(float2*)dst = make_float2(o_acc[i][0] * inv, o_acc[i][1] * inv);
    }
}

// ---------------- launch ----------------
extern "C" void kernel_launch(void* const* d_in, const int* in_sizes, int n_in,
                              void* d_out, int out_size)
{
    const float* x  = (const float*)d_in[0];
    const float* qm = (const float*)d_in[1];
    const float* km = (const float*)d_in[2];
    const float* vm = (const float*)d_in[3];
    const float* wm = (const float*)d_in[4];
    float* out = (float*)d_out;

    float *pq, *pk, *pv, *po;
    cudaGetSymbolAddress((void**)&pq, g_q);
    cudaGetSymbolAddress((void**)&pk, g_k);
    cudaGetSymbolAddress((void**)&pv, g_v);
    cudaGetSymbolAddress((void**)&po, g_o);

    const int fsmem = (3 * FR * DK_ + FR * FC) * (int)sizeof(float);  // 160KB
    cudaFuncSetAttribute(flash_kernel, cudaFuncAttributeMaxDynamicSharedMemorySize, fsmem);
    cudaFuncSetAttribute(gemm_mma_kernel, cudaFuncAttributeMaxDynamicSharedMemorySize, SM_TOTAL);

    // fused QKV projection on mma.sync (scatter to [B,H,T,DK])
    dim3 qkvGrid(HD_ / 128, M_ / 128, 3);   // (8, 32, 3)
    gemm_mma_kernel<<<qkvGrid, 512, SM_TOTAL>>>(x, qm, km, vm, pq, pk, pv, 1);

    // fused causal attention -> [B,T,H*DK]
    dim3 flashGrid(T_ / FR, B_ * H_);       // (16, 32)
    flash_kernel<<<flashGrid, 512, fsmem>>>(pq, pk, pv, po);

    // output projection on mma.sync
    dim3 oGrid(HD_ / 128, M_ / 128, 1);
    gemm_mma_kernel<<<oGrid, 512, SM_TOTAL>>>(po, wm, wm, wm, out, out, out, 0);
}

// round 9
// speedup vs baseline: 2.4801x; 1.1264x over previous
#include <cuda_runtime.h>
#include <cuda_bf16.h>
#include <stdint.h>
#include <math.h>

#define B_   2
#define T_   2048
#define C_   1024
#define H_   16
#define DK_  64
#define HD_  1024   // H_*DK_
#define M_   4096   // B_*T_
#define KDIM 1024
#define NCH  16     // KDIM / 64

// ---------------- scratch (no allocation allowed) ----------------
__device__ float g_q[(size_t)B_*H_*T_*DK_];
__device__ float g_k[(size_t)B_*H_*T_*DK_];
__device__ float g_v[(size_t)B_*H_*T_*DK_];
__device__ float g_o[(size_t)B_*T_*HD_];
// bf16 split operands
__device__ __nv_bfloat16 g_xhi[(size_t)M_*KDIM];
__device__ __nv_bfloat16 g_xlo[(size_t)M_*KDIM];
__device__ __nv_bfloat16 g_ohi[(size_t)M_*KDIM];
__device__ __nv_bfloat16 g_olo[(size_t)M_*KDIM];
__device__ __nv_bfloat16 g_whi[(size_t)4*KDIM*HD_];   // transposed [n][k], z: q,k,v,o
__device__ __nv_bfloat16 g_wlo[(size_t)4*KDIM*HD_];

// ---------------- helpers ----------------
__device__ __forceinline__ uint32_t smem_u32(const void* p) {
    uint32_t a;
    asm("{ .reg .u64 t; cvta.to.shared.u64 t, %1; cvt.u32.u64 %0, t; }"
        : "=r"(a) : "l"(p));
    return a;
}
#define SW128(o) ((uint32_t)(o) ^ ((((uint32_t)(o)) >> 3) & 0x70u))

__device__ __forceinline__ void ldm_x4(uint32_t* r, uint32_t addr) {
    asm volatile("ldmatrix.sync.aligned.m8n8.x4.shared.b16 {%0,%1,%2,%3}, [%4];"
                 : "=r"(r[0]), "=r"(r[1]), "=r"(r[2]), "=r"(r[3]) : "r"(addr));
}

__device__ __forceinline__ void mma_bf16(float* c, const uint32_t* a,
                                         uint32_t b0, uint32_t b1) {
    asm volatile(
        "mma.sync.aligned.m16n8k16.row.col.f32.bf16.bf16.f32 "
        "{%0,%1,%2,%3}, {%4,%5,%6,%7}, {%8,%9}, {%0,%1,%2,%3};"
        : "+f"(c[0]), "+f"(c[1]), "+f"(c[2]), "+f"(c[3])
        : "r"(a[0]), "r"(a[1]), "r"(a[2]), "r"(a[3]), "r"(b0), "r"(b1));
}

__device__ __forceinline__ void cp_async16(uint32_t dst, const void* src) {
    asm volatile("cp.async.cg.shared.global [%0], [%1], 16;"
                 :: "r"(dst), "l"(src));
}
#define CP_COMMIT() asm volatile("cp.async.commit_group;" ::: "memory")
#define CP_WAIT0()  asm volatile("cp.async.wait_group 0;" ::: "memory")
#define CP_WAIT1()  asm volatile("cp.async.wait_group 1;" ::: "memory")

__device__ __forceinline__ void split2(float a, float b, uint32_t& hi, uint32_t& lo) {
    __nv_bfloat16 ah = __float2bfloat16(a);
    __nv_bfloat16 bh = __float2bfloat16(b);
    __nv_bfloat16 al = __float2bfloat16(a - __bfloat162float(ah));
    __nv_bfloat16 bl = __float2bfloat16(b - __bfloat162float(bh));
    uint16_t ahb = *(uint16_t*)&ah, bhb = *(uint16_t*)&bh;
    uint16_t alb = *(uint16_t*)&al, blb = *(uint16_t*)&bl;
    hi = (uint32_t)ahb | ((uint32_t)bhb << 16);
    lo = (uint32_t)alb | ((uint32_t)blb << 16);
}

// ---------------- prep: elementwise fp32 -> bf16 hi/lo ----------------
__global__ void __launch_bounds__(256)
convert_split_kernel(const float* __restrict__ in,
                     __nv_bfloat16* __restrict__ hi,
                     __nv_bfloat16* __restrict__ lo, int n4)
{
    int i = blockIdx.x * blockDim.x + threadIdx.x;
    if (i < n4) {
        float4 v = ((const float4*)in)[i];
        uint32_t h0, l0, h1, l1;
        split2(v.x, v.y, h0, l0);
        split2(v.z, v.w, h1, l1);
        ((uint2*)hi)[i] = make_uint2(h0, h1);
        ((uint2*)lo)[i] = make_uint2(l0, l1);
    }
}

// ---------------- prep: transpose [k][n] fp32 -> [n][k] bf16 hi/lo --------
__global__ void __launch_bounds__(256)
transpose_split_kernel(const float* __restrict__ Wq,
                       const float* __restrict__ Wk,
                       const float* __restrict__ Wv,
                       const float* __restrict__ Wo,
                       __nv_bfloat16* __restrict__ hi,
                       __nv_bfloat16* __restrict__ lo)
{
    __shared__ float t[32][33];
    const int z = blockIdx.z;
    const float* W = (z == 0) ? Wq : (z == 1) ? Wk : (z == 2) ? Wv : Wo;
    __nv_bfloat16* ho = hi + (size_t)z * KDIM * HD_;
    __nv_bfloat16* lo_ = lo + (size_t)z * KDIM * HD_;

    const int k0 = blockIdx.x * 32;
    const int n0 = blockIdx.y * 32;
    const int tx = threadIdx.x, ty = threadIdx.y;

#pragma unroll
    for (int r = 0; r < 4; r++)
        t[ty + r * 8][tx] = W[(size_t)(k0 + ty + r * 8) * HD_ + n0 + tx];
    __syncthreads();
#pragma unroll
    for (int r = 0; r < 4; r++) {
        float f = t[tx][ty + r * 8];
        __nv_bfloat16 h = __float2bfloat16(f);
        __nv_bfloat16 l = __float2bfloat16(f - __bfloat162float(h));
        size_t o = (size_t)(n0 + ty + r * 8) * KDIM + k0 + tx;
        ho[o] = h;
        lo_[o] = l;
    }
}

// ---------------- bf16x3 mma.sync GEMM with cp.async pipeline -------------
// CTA 128x128, 512 threads, 16 warps (4x4), warp tile 32x32, K chunks of 64.
// smem: 2 buffers x (AHI,ALO,BHI,BLO each 16KB) = 128KB, SW128-swizzled.
#define SM_BUF 65536u
#define SM_AHI 0u
#define SM_ALO 16384u
#define SM_BHI 32768u
#define SM_BLO 49152u
#define SM_TOTAL 131072

__device__ __forceinline__ void load_chunk(
    uint32_t sbuf,
    const __nv_bfloat16* __restrict__ Ahi, const __nv_bfloat16* __restrict__ Alo,
    const __nv_bfloat16* __restrict__ Bhi, const __nv_bfloat16* __restrict__ Blo,
    int bRow, int bCol, int ch, int tid)
{
#pragma unroll
    for (int p = 0; p < 2; p++) {
        int idx = p * 512 + tid;
        int r = idx >> 3;            // 0..127
        int c = idx & 7;             // 16B chunk
        uint32_t off = SW128(r * 128 + c * 16);
        const __nv_bfloat16* a = Ahi + (size_t)(bRow * 128 + r) * KDIM + ch * 64 + c * 8;
        const __nv_bfloat16* al = Alo + (size_t)(bRow * 128 + r) * KDIM + ch * 64 + c * 8;
        const __nv_bfloat16* bh = Bhi + (size_t)(bCol * 128 + r) * KDIM + ch * 64 + c * 8;
        const __nv_bfloat16* bl = Blo + (size_t)(bCol * 128 + r) * KDIM + ch * 64 + c * 8;
        cp_async16(sbuf + SM_AHI + off, a);
        cp_async16(sbuf + SM_ALO + off, al);
        cp_async16(sbuf + SM_BHI + off, bh);
        cp_async16(sbuf + SM_BLO + off, bl);
    }
}

__global__ void __launch_bounds__(512, 1)
gemm_bf16_kernel(const __nv_bfloat16* __restrict__ Ahi,
                 const __nv_bfloat16* __restrict__ Alo,
                 float* __restrict__ C0,
                 float* __restrict__ C1,
                 float* __restrict__ C2,
                 int wzoff, int scatter)
{
    extern __shared__ char gsm[];
    const uint32_t sb = smem_u32(gsm);

    const int tid  = threadIdx.x;
    const int wid  = tid >> 5;
    const int lane = tid & 31;
    const int bRow = blockIdx.y;
    const int bCol = blockIdx.x;
    const int z    = blockIdx.z;

    const __nv_bfloat16* Bhi = g_whi + (size_t)(wzoff + z) * KDIM * HD_;
    const __nv_bfloat16* Blo = g_wlo + (size_t)(wzoff + z) * KDIM * HD_;
    float* Cout = (z == 0) ? C0 : (z == 1) ? C1 : C2;

    const int m0 = (wid >> 2) * 32;
    const int n0 = (wid & 3) * 32;

    float acc[2][4][4];
#pragma unroll
    for (int mt = 0; mt < 2; mt++)
#pragma unroll
        for (int j = 0; j < 4; j++)
#pragma unroll
            for (int r = 0; r < 4; r++) acc[mt][j][r] = 0.0f;

    load_chunk(sb, Ahi, Alo, Bhi, Blo, bRow, bCol, 0, tid);
    CP_COMMIT();
    load_chunk(sb + SM_BUF, Ahi, Alo, Bhi, Blo, bRow, bCol, 1, tid);
    CP_COMMIT();

    for (int ch = 0; ch < NCH; ch++) {
        const uint32_t sbuf = sb + (ch & 1) * SM_BUF;
        if (ch == NCH - 1) CP_WAIT0(); else CP_WAIT1();
        __syncthreads();

        // ---- MMA phase: 4 k16 steps, bf16x3 ----
#pragma unroll
        for (int ks = 0; ks < 4; ks++) {
            const uint32_t colb = ks * 32 + (lane >> 4) * 16;
            uint32_t ahi[2][4], alo[2][4], bhi[2][4], blo[2][4];
#pragma unroll
            for (int mt = 0; mt < 2; mt++) {
                uint32_t roff = (uint32_t)(m0 + mt * 16 + (lane & 15)) * 128 + colb;
                ldm_x4(ahi[mt], sbuf + SM_AHI + SW128(roff));
                ldm_x4(alo[mt], sbuf + SM_ALO + SW128(roff));
            }
#pragma unroll
            for (int nt = 0; nt < 2; nt++) {
                uint32_t roff = (uint32_t)(n0 + nt * 16 + (lane & 15)) * 128 + colb;
                ldm_x4(bhi[nt], sbuf + SM_BHI + SW128(roff));
                ldm_x4(blo[nt], sbuf + SM_BLO + SW128(roff));
            }
#pragma unroll
            for (int mt = 0; mt < 2; mt++)
#pragma unroll
                for (int j = 0; j < 4; j++)
                    mma_bf16(acc[mt][j], ahi[mt], bhi[j >> 1][j & 1], bhi[j >> 1][(j & 1) + 2]);
#pragma unroll
            for (int mt = 0; mt < 2; mt++)
#pragma unroll
                for (int j = 0; j < 4; j++)
                    mma_bf16(acc[mt][j], ahi[mt], blo[j >> 1][j & 1], blo[j >> 1][(j & 1) + 2]);
#pragma unroll
            for (int mt = 0; mt < 2; mt++)
#pragma unroll
                for (int j = 0; j < 4; j++)
                    mma_bf16(acc[mt][j], alo[mt], bhi[j >> 1][j & 1], bhi[j >> 1][(j & 1) + 2]);
        }
        __syncthreads();
        if (ch + 2 < NCH) {
            load_chunk(sbuf, Ahi, Alo, Bhi, Blo, bRow, bCol, ch + 2, tid);
            CP_COMMIT();
        }
    }

    // ---- epilogue: C fragment -> gmem float2 ----
#pragma unroll
    for (int mt = 0; mt < 2; mt++) {
#pragma unroll
        for (int j = 0; j < 4; j++) {
            int row = bRow * 128 + m0 + mt * 16 + (lane >> 2);
            int col = bCol * 128 + n0 + j * 8 + (lane & 3) * 2;
#pragma unroll
            for (int half = 0; half < 2; half++) {
                int rr = row + half * 8;
                float2 v = make_float2(acc[mt][j][half * 2], acc[mt][j][half * 2 + 1]);
                if (scatter) {
                    int b = rr >> 11, t = rr & 2047, h = col >> 6, d = col & 63;
                    *(float2*)(Cout + (((size_t)(b * H_ + h) * T_ + t) * DK_ + d)) = v;
                } else {
                    *(float2*)(Cout + (size_t)rr * HD_ + col) = v;
                }
            }
        }
    }
}

// ---------------- flash attention fp32, 512 threads (round-5 proven) -------
#define FR 128
#define FC 128

__global__ __launch_bounds__(512, 1)
void flash_kernel(const float* __restrict__ q,
                  const float* __restrict__ k,
                  const float* __restrict__ v,
                  float* __restrict__ o)
{
    extern __shared__ float fsm[];
    float* Qs = fsm;
    float* Ks = Qs + FR * DK_;
    float* Vs = Ks + FC * DK_;
    float* Ps = Vs + FC * DK_;

    const int qt = (gridDim.x - 1) - blockIdx.x;
    const int bh = blockIdx.y;
    const int b  = bh / H_;
    const int h  = bh % H_;

    const float* qb = q + (size_t)bh * T_ * DK_;
    const float* kb = k + (size_t)bh * T_ * DK_;
    const float* vb = v + (size_t)bh * T_ * DK_;

    const int tid  = threadIdx.x;
    const int w    = tid >> 5;
    const int lane = tid & 31;
    const int i0   = qt * FR;

    const int ksw  = (lane & 7) * 4;
    const int qsw0 = ((w * 2) & 7) * 4;
    const int qsw1 = ((w * 2 + 1) & 7) * 4;

#pragma unroll
    for (int l = 0; l < 4; l++) {
        int idx = l * 512 + tid;
        int r = idx >> 4;
        int d = (idx & 15) * 4;
        float4 t4 = *(const float4*)(qb + (size_t)(i0 + r) * DK_ + d);
        *(float4*)&Qs[r * 64 + (d ^ (((r >> 2) & 7) * 4))] =
            make_float4(t4.x * 8.0f, t4.y * 8.0f, t4.z * 8.0f, t4.w * 8.0f);
    }

    float m_i[8], l_i[8], o_acc[8][2];
#pragma unroll
    for (int i = 0; i < 8; i++) {
        m_i[i] = -1e30f;
        l_i[i] = 0.0f;
        o_acc[i][0] = 0.0f;
        o_acc[i][1] = 0.0f;
    }

    for (int jt = 0; jt <= qt; jt++) {
        const int j0 = jt * FC;
#pragma unroll
        for (int l = 0; l < 4; l++) {
            int idx = l * 512 + tid;
            int r = idx >> 4;
            int d = (idx & 15) * 4;
            *(float4*)&Ks[r * 64 + (d ^ (((r >> 2) & 7) * 4))] =
                *(const float4*)(kb + (size_t)(j0 + r) * DK_ + d);
            *(float4*)&Vs[r * 64 + d] =
                *(const float4*)(vb + (size_t)(j0 + r) * DK_ + d);
        }
        __syncthreads();

        float s[8][4];
#pragma unroll
        for (int i = 0; i < 8; i++)
#pragma unroll
            for (int j = 0; j < 4; j++) s[i][j] = 0.0f;

#pragma unroll 4
        for (int d = 0; d < DK_; d += 4) {
            float4 kv[4];
#pragma unroll
            for (int j = 0; j < 4; j++)
                kv[j] = *(const float4*)&Ks[(lane * 4 + j) * 64 + (d ^ ksw)];
#pragma unroll
            for (int i = 0; i < 8; i++) {
                float4 qv = *(const float4*)&Qs[(w * 8 + i) * 64 +
                                                (d ^ (i < 4 ? qsw0 : qsw1))];
#pragma unroll
                for (int j = 0; j < 4; j++) {
                    s[i][j] = fmaf(qv.x, kv[j].x, s[i][j]);
                    s[i][j] = fmaf(qv.y, kv[j].y, s[i][j]);
                    s[i][j] = fmaf(qv.z, kv[j].z, s[i][j]);
                    s[i][j] = fmaf(qv.w, kv[j].w, s[i][j]);
                }
            }
        }

        if (jt == qt) {
#pragma unroll
            for (int i = 0; i < 8; i++)
#pragma unroll
                for (int j = 0; j < 4; j++)
                    if (lane * 4 + j > w * 8 + i) s[i][j] = -1e30f;
        }

#pragma unroll
        for (int i = 0; i < 8; i++) {
            float mn = fmaxf(fmaxf(s[i][0], s[i][1]), fmaxf(s[i][2], s[i][3]));
#pragma unroll
            for (int off = 16; off >= 1; off >>= 1)
                mn = fmaxf(mn, __shfl_xor_sync(0xffffffffu, mn, off));

            float mnew = fmaxf(m_i[i], mn);
            float corr = __expf(m_i[i] - mnew);
            m_i[i] = mnew;

            float p0 = __expf(s[i][0] - mnew);
            float p1 = __expf(s[i][1] - mnew);
            float p2 = __expf(s[i][2] - mnew);
            float p3 = __expf(s[i][3] - mnew);
            *(float4*)&Ps[(w * 8 + i) * FC + lane * 4] = make_float4(p0, p1, p2, p3);

            float rs = p0 + p1 + p2 + p3;
#pragma unroll
            for (int off = 16; off >= 1; off >>= 1)
                rs += __shfl_xor_sync(0xffffffffu, rs, off);

            l_i[i] = l_i[i] * corr + rs;
            o_acc[i][0] *= corr;
            o_acc[i][1] *= corr;
        }
        __syncwarp();

#pragma unroll 4
        for (int kk = 0; kk < FC; kk += 4) {
            float2 v0 = *(const float2*)&Vs[(kk + 0) * 64 + lane * 2];
            float2 v1 = *(const float2*)&Vs[(kk + 1) * 64 + lane * 2];
            float2 v2 = *(const float2*)&Vs[(kk + 2) * 64 + lane * 2];
            float2 v3 = *(const float2*)&Vs[(kk + 3) * 64 + lane * 2];
#pragma unroll
            for (int i = 0; i < 8; i++) {
                float4 p4 = *(const float4*)&Ps[(w * 8 + i) * FC + kk];
                o_acc[i][0] = fmaf(p4.x, v0.x, o_acc[i][0]);
                o_acc[i][1] = fmaf(p4.x, v0.y, o_acc[i][1]);
                o_acc[i][0] = fmaf(p4.y, v1.x, o_acc[i][0]);
                o_acc[i][1] = fmaf(p4.y, v1.y, o_acc[i][1]);
                o_acc[i][0] = fmaf(p4.z, v2.x, o_acc[i][0]);
                o_acc[i][1] = fmaf(p4.z, v2.y, o_acc[i][1]);
                o_acc[i][0] = fmaf(p4.w, v3.x, o_acc[i][0]);
                o_acc[i][1] = fmaf(p4.w, v3.y, o_acc[i][1]);
            }
        }
        __syncthreads();
    }

#pragma unroll
    for (int i = 0; i < 8; i++) {
        float inv = 1.0f / l_i[i];
        int t = i0 + w * 8 + i;
        float* dst = o + (size_t)(b * T_ + t) * HD_ + h * DK_ + lane * 2;
        *(float2*)dst = make_float2(o_acc[i][0] * inv, o_acc[i][1] * inv);
    }
}

// ---------------- launch ----------------
extern "C" void kernel_launch(void* const* d_in, const int* in_sizes, int n_in,
                              void* d_out, int out_size)
{
    const float* x  = (const float*)d_in[0];
    const float* qm = (const float*)d_in[1];
    const float* km = (const float*)d_in[2];
    const float* vm = (const float*)d_in[3];
    const float* wm = (const float*)d_in[4];
    float* out = (float*)d_out;

    float *pq, *pk, *pv, *po;
    __nv_bfloat16 *xhi, *xlo, *ohi, *olo, *whi, *wlo;
    cudaGetSymbolAddress((void**)&pq, g_q);
    cudaGetSymbolAddress((void**)&pk, g_k);
    cudaGetSymbolAddress((void**)&pv, g_v);
    cudaGetSymbolAddress((void**)&po, g_o);
    cudaGetSymbolAddress((void**)&xhi, g_xhi);
    cudaGetSymbolAddress((void**)&xlo, g_xlo);
    cudaGetSymbolAddress((void**)&ohi, g_ohi);
    cudaGetSymbolAddress((void**)&olo, g_olo);
    cudaGetSymbolAddress((void**)&whi, g_whi);
    cudaGetSymbolAddress((void**)&wlo, g_wlo);

    const int fsmem = (3 * FR * DK_ + FR * FC) * (int)sizeof(float);  // 160KB
    cudaFuncSetAttribute(flash_kernel, cudaFuncAttributeMaxDynamicSharedMemorySize, fsmem);
    cudaFuncSetAttribute(gemm_bf16_kernel, cudaFuncAttributeMaxDynamicSharedMemorySize, SM_TOTAL);

    // prep: x -> bf16 hi/lo ; weights -> transposed bf16 hi/lo
    const int n4 = M_ * KDIM / 4;
    convert_split_kernel<<<(n4 + 255) / 256, 256>>>(x, xhi, xlo, n4);
    dim3 tGrid(KDIM / 32, HD_ / 32, 4);
    transpose_split_kernel<<<tGrid, dim3(32, 8)>>>(qm, km, vm, wm, whi, wlo);

    // fused QKV projection (tensor cores, scatter to [B,H,T,DK])
    dim3 qkvGrid(HD_ / 128, M_ / 128, 3);
    gemm_bf16_kernel<<<qkvGrid, 512, SM_TOTAL>>>(xhi, xlo, pq, pk, pv, 0, 1);

    // fused causal attention -> [B,T,H*DK]
    dim3 flashGrid(T_ / FR, B_ * H_);
    flash_kernel<<<flashGrid, 512, fsmem>>>(pq, pk, pv, po);

    // o -> bf16 hi/lo, then output projection
    convert_split_kernel<<<(n4 + 255) / 256, 256>>>(po, ohi, olo, n4);
    dim3 oGrid(HD_ / 128, M_ / 128, 1);
    gemm_bf16_kernel<<<oGrid, 512, SM_TOTAL>>>(ohi, olo, out, out, out, 3, 0);
}

// round 11
// speedup vs baseline: 4.1643x; 1.6790x over previous
#include <cuda_runtime.h>
#include <cuda_bf16.h>
#include <stdint.h>
#include <math.h>

#define B_   2
#define T_   2048
#define C_   1024
#define H_   16
#define DK_  64
#define HD_  1024   // H_*DK_
#define M_   4096   // B_*T_
#define KDIM 1024
#define NCH  16     // KDIM / 64

// ---------------- scratch (no allocation allowed) ----------------
__device__ __nv_bfloat16 g_qhi[(size_t)B_*H_*T_*DK_];
__device__ __nv_bfloat16 g_qlo[(size_t)B_*H_*T_*DK_];
__device__ __nv_bfloat16 g_khi[(size_t)B_*H_*T_*DK_];
__device__ __nv_bfloat16 g_klo[(size_t)B_*H_*T_*DK_];
__device__ __nv_bfloat16 g_vhi[(size_t)B_*H_*T_*DK_];
__device__ __nv_bfloat16 g_vlo[(size_t)B_*H_*T_*DK_];
__device__ __nv_bfloat16 g_ohi[(size_t)M_*HD_];
__device__ __nv_bfloat16 g_olo[(size_t)M_*HD_];
__device__ __nv_bfloat16 g_xhi[(size_t)M_*KDIM];
__device__ __nv_bfloat16 g_xlo[(size_t)M_*KDIM];
__device__ __nv_bfloat16 g_whi[(size_t)4*KDIM*HD_];   // transposed [n][k]; z: q,k,v,o
__device__ __nv_bfloat16 g_wlo[(size_t)4*KDIM*HD_];

// ---------------- helpers ----------------
__device__ __forceinline__ uint32_t smem_u32(const void* p) {
    uint32_t a;
    asm("{ .reg .u64 t; cvta.to.shared.u64 t, %1; cvt.u32.u64 %0, t; }"
        : "=r"(a) : "l"(p));
    return a;
}
#define SW128(o) ((uint32_t)(o) ^ ((((uint32_t)(o)) >> 3) & 0x70u))

__device__ __forceinline__ void ldm_x4(uint32_t* r, uint32_t addr) {
    asm volatile("ldmatrix.sync.aligned.m8n8.x4.shared.b16 {%0,%1,%2,%3}, [%4];"
                 : "=r"(r[0]), "=r"(r[1]), "=r"(r[2]), "=r"(r[3]) : "r"(addr));
}
__device__ __forceinline__ void ldm_x4_trans(uint32_t* r, uint32_t addr) {
    asm volatile("ldmatrix.sync.aligned.m8n8.x4.trans.shared.b16 {%0,%1,%2,%3}, [%4];"
                 : "=r"(r[0]), "=r"(r[1]), "=r"(r[2]), "=r"(r[3]) : "r"(addr));
}

__device__ __forceinline__ void mma_bf16(float* c, const uint32_t* a,
                                         uint32_t b0, uint32_t b1) {
    asm volatile(
        "mma.sync.aligned.m16n8k16.row.col.f32.bf16.bf16.f32 "
        "{%0,%1,%2,%3}, {%4,%5,%6,%7}, {%8,%9}, {%0,%1,%2,%3};"
        : "+f"(c[0]), "+f"(c[1]), "+f"(c[2]), "+f"(c[3])
        : "r"(a[0]), "r"(a[1]), "r"(a[2]), "r"(a[3]), "r"(b0), "r"(b1));
}

__device__ __forceinline__ void cp_async16(uint32_t dst, const void* src) {
    asm volatile("cp.async.cg.shared.global [%0], [%1], 16;"
                 :: "r"(dst), "l"(src));
}
#define CP_COMMIT() asm volatile("cp.async.commit_group;" ::: "memory")
#define CP_WAIT0()  asm volatile("cp.async.wait_group 0;" ::: "memory")
#define CP_WAIT1()  asm volatile("cp.async.wait_group 1;" ::: "memory")

__device__ __forceinline__ void split2(float a, float b, uint32_t& hi, uint32_t& lo) {
    __nv_bfloat16 ah = __float2bfloat16(a);
    __nv_bfloat16 bh = __float2bfloat16(b);
    __nv_bfloat16 al = __float2bfloat16(a - __bfloat162float(ah));
    __nv_bfloat16 bl = __float2bfloat16(b - __bfloat162float(bh));
    uint16_t ahb = *(uint16_t*)&ah, bhb = *(uint16_t*)&bh;
    uint16_t alb = *(uint16_t*)&al, blb = *(uint16_t*)&bl;
    hi = (uint32_t)ahb | ((uint32_t)bhb << 16);
    lo = (uint32_t)alb | ((uint32_t)blb << 16);
}

// ---------------- prep kernels (round-9 proven) ----------------
__global__ void __launch_bounds__(256)
convert_split_kernel(const float* __restrict__ in,
                     __nv_bfloat16* __restrict__ hi,
                     __nv_bfloat16* __restrict__ lo, int n4)
{
    int i = blockIdx.x * blockDim.x + threadIdx.x;
    if (i < n4) {
        float4 v = ((const float4*)in)[i];
        uint32_t h0, l0, h1, l1;
        split2(v.x, v.y, h0, l0);
        split2(v.z, v.w, h1, l1);
        ((uint2*)hi)[i] = make_uint2(h0, h1);
        ((uint2*)lo)[i] = make_uint2(l0, l1);
    }
}

__global__ void __launch_bounds__(256)
transpose_split_kernel(const float* __restrict__ Wq,
                       const float* __restrict__ Wk,
                       const float* __restrict__ Wv,
                       const float* __restrict__ Wo,
                       __nv_bfloat16* __restrict__ hi,
                       __nv_bfloat16* __restrict__ lo)
{
    __shared__ float t[32][33];
    const int z = blockIdx.z;
    const float* W = (z == 0) ? Wq : (z == 1) ? Wk : (z == 2) ? Wv : Wo;
    __nv_bfloat16* ho = hi + (size_t)z * KDIM * HD_;
    __nv_bfloat16* lo_ = lo + (size_t)z * KDIM * HD_;

    const int k0 = blockIdx.x * 32;
    const int n0 = blockIdx.y * 32;
    const int tx = threadIdx.x, ty = threadIdx.y;

#pragma unroll
    for (int r = 0; r < 4; r++)
        t[ty + r * 8][tx] = W[(size_t)(k0 + ty + r * 8) * HD_ + n0 + tx];
    __syncthreads();
#pragma unroll
    for (int r = 0; r < 4; r++) {
        float f = t[tx][ty + r * 8];
        __nv_bfloat16 h = __float2bfloat16(f);
        __nv_bfloat16 l = __float2bfloat16(f - __bfloat162float(h));
        size_t o = (size_t)(n0 + ty + r * 8) * KDIM + k0 + tx;
        ho[o] = h;
        lo_[o] = l;
    }
}

// ---------------- bf16x3 mma.sync GEMM (round-9 proven core) --------------
#define SM_BUF 65536u
#define SM_AHI 0u
#define SM_ALO 16384u
#define SM_BHI 32768u
#define SM_BLO 49152u
#define SM_TOTAL 131072

__device__ __forceinline__ void load_chunk(
    uint32_t sbuf,
    const __nv_bfloat16* __restrict__ Ahi, const __nv_bfloat16* __restrict__ Alo,
    const __nv_bfloat16* __restrict__ Bhi, const __nv_bfloat16* __restrict__ Blo,
    int bRow, int bCol, int ch, int tid)
{
#pragma unroll
    for (int p = 0; p < 2; p++) {
        int idx = p * 512 + tid;
        int r = idx >> 3;
        int c = idx & 7;
        uint32_t off = SW128(r * 128 + c * 16);
        cp_async16(sbuf + SM_AHI + off, Ahi + (size_t)(bRow * 128 + r) * KDIM + ch * 64 + c * 8);
        cp_async16(sbuf + SM_ALO + off, Alo + (size_t)(bRow * 128 + r) * KDIM + ch * 64 + c * 8);
        cp_async16(sbuf + SM_BHI + off, Bhi + (size_t)(bCol * 128 + r) * KDIM + ch * 64 + c * 8);
        cp_async16(sbuf + SM_BLO + off, Blo + (size_t)(bCol * 128 + r) * KDIM + ch * 64 + c * 8);
    }
}

__global__ void __launch_bounds__(512, 1)
gemm_bf16_kernel(const __nv_bfloat16* __restrict__ Ahi,
                 const __nv_bfloat16* __restrict__ Alo,
                 __nv_bfloat16* __restrict__ S0h, __nv_bfloat16* __restrict__ S0l,
                 __nv_bfloat16* __restrict__ S1h, __nv_bfloat16* __restrict__ S1l,
                 __nv_bfloat16* __restrict__ S2h, __nv_bfloat16* __restrict__ S2l,
                 float* __restrict__ Cout,
                 int wzoff, int scatter)
{
    extern __shared__ char gsm[];
    const uint32_t sb = smem_u32(gsm);

    const int tid  = threadIdx.x;
    const int wid  = tid >> 5;
    const int lane = tid & 31;
    const int bRow = blockIdx.y;
    const int bCol = blockIdx.x;
    const int z    = blockIdx.z;

    const __nv_bfloat16* Bhi = g_whi + (size_t)(wzoff + z) * KDIM * HD_;
    const __nv_bfloat16* Blo = g_wlo + (size_t)(wzoff + z) * KDIM * HD_;

    const int m0 = (wid >> 2) * 32;
    const int n0 = (wid & 3) * 32;

    float acc[2][4][4];
#pragma unroll
    for (int mt = 0; mt < 2; mt++)
#pragma unroll
        for (int j = 0; j < 4; j++)
#pragma unroll
            for (int r = 0; r < 4; r++) acc[mt][j][r] = 0.0f;

    load_chunk(sb, Ahi, Alo, Bhi, Blo, bRow, bCol, 0, tid);
    CP_COMMIT();
    load_chunk(sb + SM_BUF, Ahi, Alo, Bhi, Blo, bRow, bCol, 1, tid);
    CP_COMMIT();

    for (int ch = 0; ch < NCH; ch++) {
        const uint32_t sbuf = sb + (ch & 1) * SM_BUF;
        if (ch == NCH - 1) CP_WAIT0(); else CP_WAIT1();
        __syncthreads();

#pragma unroll
        for (int ks = 0; ks < 4; ks++) {
            const uint32_t colb = ks * 32 + (lane >> 4) * 16;
            uint32_t ahi[2][4], alo[2][4], bhi4[2][4], blo4[2][4];
#pragma unroll
            for (int mt = 0; mt < 2; mt++) {
                uint32_t roff = (uint32_t)(m0 + mt * 16 + (lane & 15)) * 128 + colb;
                ldm_x4(ahi[mt], sbuf + SM_AHI + SW128(roff));
                ldm_x4(alo[mt], sbuf + SM_ALO + SW128(roff));
            }
#pragma unroll
            for (int nt = 0; nt < 2; nt++) {
                uint32_t roff = (uint32_t)(n0 + nt * 16 + (lane & 15)) * 128 + colb;
                ldm_x4(bhi4[nt], sbuf + SM_BHI + SW128(roff));
                ldm_x4(blo4[nt], sbuf + SM_BLO + SW128(roff));
            }
#pragma unroll
            for (int mt = 0; mt < 2; mt++)
#pragma unroll
                for (int j = 0; j < 4; j++)
                    mma_bf16(acc[mt][j], ahi[mt], bhi4[j >> 1][j & 1], bhi4[j >> 1][(j & 1) + 2]);
#pragma unroll
            for (int mt = 0; mt < 2; mt++)
#pragma unroll
                for (int j = 0; j < 4; j++)
                    mma_bf16(acc[mt][j], ahi[mt], blo4[j >> 1][j & 1], blo4[j >> 1][(j & 1) + 2]);
#pragma unroll
            for (int mt = 0; mt < 2; mt++)
#pragma unroll
                for (int j = 0; j < 4; j++)
                    mma_bf16(acc[mt][j], alo[mt], bhi4[j >> 1][j & 1], bhi4[j >> 1][(j & 1) + 2]);
        }
        __syncthreads();
        if (ch + 2 < NCH) {
            load_chunk(sbuf, Ahi, Alo, Bhi, Blo, bRow, bCol, ch + 2, tid);
            CP_COMMIT();
        }
    }

    // epilogue
    __nv_bfloat16* Dh = (z == 0) ? S0h : (z == 1) ? S1h : S2h;
    __nv_bfloat16* Dl = (z == 0) ? S0l : (z == 1) ? S1l : S2l;
    const float sc = (scatter && z == 0) ? 8.0f : 1.0f;   // fold sqrt(dk) into q
#pragma unroll
    for (int mt = 0; mt < 2; mt++) {
#pragma unroll
        for (int j = 0; j < 4; j++) {
            int row = bRow * 128 + m0 + mt * 16 + (lane >> 2);
            int col = bCol * 128 + n0 + j * 8 + (lane & 3) * 2;
#pragma unroll
            for (int half = 0; half < 2; half++) {
                int rr = row + half * 8;
                float vx = acc[mt][j][half * 2], vy = acc[mt][j][half * 2 + 1];
                if (scatter) {
                    int b = rr >> 11, t = rr & 2047, h = col >> 6, d = col & 63;
                    size_t off = ((size_t)(b * H_ + h) * T_ + t) * DK_ + d;
                    uint32_t hi, lo;
                    split2(vx * sc, vy * sc, hi, lo);
                    *(uint32_t*)(Dh + off) = hi;
                    *(uint32_t*)(Dl + off) = lo;
                } else {
                    *(float2*)(Cout + (size_t)rr * HD_ + col) = make_float2(vx, vy);
                }
            }
        }
    }
}

// ---------------- flash attention on mma.sync (bf16x3) ----------------
// 256 threads, 8 warps; warp w owns q-rows w*16..+15 of a 128-row tile.
// K-tiles of 64 keys, cp.async double-buffered. S and PV both bf16x3.
#define SM_QHI 0u
#define SM_QLO 16384u
#define SM_KV  32768u
#define KV_KHI 0u
#define KV_KLO 8192u
#define KV_VHI 16384u
#define KV_VLO 24576u
#define KV_STRIDE 32768u
#define FSM_TOTAL 98304

__device__ __forceinline__ void load_kv(
    uint32_t kvbuf, const __nv_bfloat16* kh, const __nv_bfloat16* kl,
    const __nv_bfloat16* vh, const __nv_bfloat16* vl, int j0, int tid)
{
#pragma unroll
    for (int p = 0; p < 2; p++) {
        int idx = p * 256 + tid;
        int r = idx >> 3;             // 0..63
        int c = idx & 7;
        uint32_t off = SW128(r * 128 + c * 16);
        size_t src = (size_t)(j0 + r) * DK_ + c * 8;
        cp_async16(kvbuf + KV_KHI + off, kh + src);
        cp_async16(kvbuf + KV_KLO + off, kl + src);
        cp_async16(kvbuf + KV_VHI + off, vh + src);
        cp_async16(kvbuf + KV_VLO + off, vl + src);
    }
}

__global__ void __launch_bounds__(256, 2)
flash_mma_kernel(const __nv_bfloat16* __restrict__ qhi, const __nv_bfloat16* __restrict__ qlo,
                 const __nv_bfloat16* __restrict__ khi, const __nv_bfloat16* __restrict__ klo,
                 const __nv_bfloat16* __restrict__ vhi, const __nv_bfloat16* __restrict__ vlo,
                 __nv_bfloat16* __restrict__ ohi, __nv_bfloat16* __restrict__ olo)
{
    extern __shared__ char fsm[];
    const uint32_t sb = smem_u32(fsm);
    const int tid  = threadIdx.x;
    const int w    = tid >> 5;
    const int lane = tid & 31;
    const int qt   = (gridDim.x - 1) - blockIdx.x;   // heavy tiles first
    const int bh   = blockIdx.y;
    const int i0   = qt * 128;

    const __nv_bfloat16* qh = qhi + (size_t)bh * T_ * DK_;
    const __nv_bfloat16* ql = qlo + (size_t)bh * T_ * DK_;
    const __nv_bfloat16* kh = khi + (size_t)bh * T_ * DK_;
    const __nv_bfloat16* kl = klo + (size_t)bh * T_ * DK_;
    const __nv_bfloat16* vh = vhi + (size_t)bh * T_ * DK_;
    const __nv_bfloat16* vl = vlo + (size_t)bh * T_ * DK_;

    // load Q tile once (128 rows x 64 d, hi+lo)
#pragma unroll
    for (int p = 0; p < 4; p++) {
        int idx = p * 256 + tid;
        int r = idx >> 3;             // 0..127
        int c = idx & 7;
        uint32_t off = SW128(r * 128 + c * 16);
        size_t src = (size_t)(i0 + r) * DK_ + c * 8;
        cp_async16(sb + SM_QHI + off, qh + src);
        cp_async16(sb + SM_QLO + off, ql + src);
    }
    CP_COMMIT();

    const int nkt = 2 * (qt + 1);     // 64-key tiles
    load_kv(sb + SM_KV, kh, kl, vh, vl, 0, tid);
    CP_COMMIT();
    if (nkt > 1) {
        load_kv(sb + SM_KV + KV_STRIDE, kh, kl, vh, vl, 64, tid);
        CP_COMMIT();
    }

    float m_i[2] = {-1e30f, -1e30f};
    float l_i[2] = {0.0f, 0.0f};
    float o_acc[8][4];
#pragma unroll
    for (int f = 0; f < 8; f++)
#pragma unroll
        for (int r = 0; r < 4; r++) o_acc[f][r] = 0.0f;

    const int row0 = i0 + w * 16 + (lane >> 2);   // global q row (half 0)

    for (int jt = 0; jt < nkt; jt++) {
        const uint32_t kvbuf = sb + SM_KV + (uint32_t)(jt & 1) * KV_STRIDE;
        const int j0 = jt * 64;
        if (jt + 1 < nkt) CP_WAIT1(); else CP_WAIT0();
        __syncthreads();

        // ---- S = Q K^T : m16 x n64, 4 k16 steps, bf16x3 ----
        float s[8][4];
#pragma unroll
        for (int f = 0; f < 8; f++)
#pragma unroll
            for (int r = 0; r < 4; r++) s[f][r] = 0.0f;

#pragma unroll
        for (int ks = 0; ks < 4; ks++) {
            const uint32_t colb = ks * 32 + (lane >> 4) * 16;
            uint32_t aqh[4], aql[4];
            uint32_t roff = (uint32_t)(w * 16 + (lane & 15)) * 128 + colb;
            ldm_x4(aqh, sb + SM_QHI + SW128(roff));
            ldm_x4(aql, sb + SM_QLO + SW128(roff));
#pragma unroll
            for (int nt = 0; nt < 4; nt++) {
                uint32_t kh4[4], kl4[4];
                uint32_t noff = (uint32_t)(nt * 16 + (lane & 15)) * 128 + colb;
                ldm_x4(kh4, kvbuf + KV_KHI + SW128(noff));
                ldm_x4(kl4, kvbuf + KV_KLO + SW128(noff));
#pragma unroll
                for (int h = 0; h < 2; h++) {
                    int f = nt * 2 + h;
                    mma_bf16(s[f], aqh, kh4[h], kh4[h + 2]);
                    mma_bf16(s[f], aqh, kl4[h], kl4[h + 2]);
                    mma_bf16(s[f], aql, kh4[h], kh4[h + 2]);
                }
            }
        }

        // ---- causal mask (only tiles at/after the diagonal) ----
        if (j0 >= i0) {
#pragma unroll
            for (int f = 0; f < 8; f++) {
                int colg = j0 + f * 8 + (lane & 3) * 2;
                if (colg     > row0)     s[f][0] = -1e30f;
                if (colg + 1 > row0)     s[f][1] = -1e30f;
                if (colg     > row0 + 8) s[f][2] = -1e30f;
                if (colg + 1 > row0 + 8) s[f][3] = -1e30f;
            }
        }

        // ---- online softmax (rows row0, row0+8) ----
#pragma unroll
        for (int half = 0; half < 2; half++) {
            float mn = -1e30f;
#pragma unroll
            for (int f = 0; f < 8; f++)
                mn = fmaxf(mn, fmaxf(s[f][half * 2], s[f][half * 2 + 1]));
            mn = fmaxf(mn, __shfl_xor_sync(0xffffffffu, mn, 1));
            mn = fmaxf(mn, __shfl_xor_sync(0xffffffffu, mn, 2));

            float mnew = fmaxf(m_i[half], mn);
            float corr = __expf(m_i[half] - mnew);
            m_i[half] = mnew;

            float rs = 0.0f;
#pragma unroll
            for (int f = 0; f < 8; f++) {
                float p0 = __expf(s[f][half * 2]     - mnew);
                float p1 = __expf(s[f][half * 2 + 1] - mnew);
                s[f][half * 2]     = p0;
                s[f][half * 2 + 1] = p1;
                rs += p0 + p1;
            }
            rs += __shfl_xor_sync(0xffffffffu, rs, 1);
            rs += __shfl_xor_sync(0xffffffffu, rs, 2);

            l_i[half] = l_i[half] * corr + rs;
#pragma unroll
            for (int f = 0; f < 8; f++) {
                o_acc[f][half * 2]     *= corr;
                o_acc[f][half * 2 + 1] *= corr;
            }
        }

        // ---- O += P V : 4 k16 steps over keys, bf16x3 ----
#pragma unroll
        for (int ks = 0; ks < 4; ks++) {
            // P A-frags from s[2ks], s[2ks+1] (in-register split)
            uint32_t ph[4], pl[4];
            split2(s[2 * ks][0],     s[2 * ks][1],     ph[0], pl[0]);
            split2(s[2 * ks][2],     s[2 * ks][3],     ph[1], pl[1]);
            split2(s[2 * ks + 1][0], s[2 * ks + 1][1], ph[2], pl[2]);
            split2(s[2 * ks + 1][2], s[2 * ks + 1][3], ph[3], pl[3]);
#pragma unroll
            for (int dt = 0; dt < 4; dt++) {
                uint32_t vh4[4], vl4[4];
                uint32_t voff = (uint32_t)(ks * 16 + (lane & 15)) * 128
                              + dt * 32 + (lane >> 4) * 16;
                ldm_x4_trans(vh4, kvbuf + KV_VHI + SW128(voff));
                ldm_x4_trans(vl4, kvbuf + KV_VLO + SW128(voff));
#pragma unroll
                for (int h = 0; h < 2; h++) {
                    int f = dt * 2 + h;
                    mma_bf16(o_acc[f], ph, vh4[h * 2], vh4[h * 2 + 1]);
                    mma_bf16(o_acc[f], ph, vl4[h * 2], vl4[h * 2 + 1]);
                    mma_bf16(o_acc[f], pl, vh4[h * 2], vh4[h * 2 + 1]);
                }
            }
        }
        __syncthreads();
        if (jt + 2 < nkt) {
            load_kv(kvbuf, kh, kl, vh, vl, (jt + 2) * 64, tid);
            CP_COMMIT();
        }
    }

    // ---- write O as bf16 hi/lo to [B,T,H*DK] ----
    const float inv0 = 1.0f / l_i[0];
    const float inv1 = 1.0f / l_i[1];
    const int b = bh >> 4, h = bh & 15;
    const int t0 = i0 + w * 16 + (lane >> 2);
#pragma unroll
    for (int f = 0; f < 8; f++) {
        int d = h * 64 + f * 8 + (lane & 3) * 2;
        uint32_t hi, lo;
        size_t off0 = ((size_t)(b * T_ + t0)) * HD_ + d;
        split2(o_acc[f][0] * inv0, o_acc[f][1] * inv0, hi, lo);
        *(uint32_t*)(ohi + off0) = hi;
        *(uint32_t*)(olo + off0) = lo;
        size_t off1 = off0 + (size_t)8 * HD_;
        split2(o_acc[f][2] * inv1, o_acc[f][3] * inv1, hi, lo);
        *(uint32_t*)(ohi + off1) = hi;
        *(uint32_t*)(olo + off1) = lo;
    }
}

// ---------------- launch ----------------
extern "C" void kernel_launch(void* const* d_in, const int* in_sizes, int n_in,
                              void* d_out, int out_size)
{
    const float* x  = (const float*)d_in[0];
    const float* qm = (const float*)d_in[1];
    const float* km = (const float*)d_in[2];
    const float* vm = (const float*)d_in[3];
    const float* wm = (const float*)d_in[4];
    float* out = (float*)d_out;

    __nv_bfloat16 *qhi, *qlo, *khi, *klo, *vhi, *vlo, *ohi, *olo, *xhi, *xlo, *whi, *wlo;
    cudaGetSymbolAddress((void**)&qhi, g_qhi);
    cudaGetSymbolAddress((void**)&qlo, g_qlo);
    cudaGetSymbolAddress((void**)&khi, g_khi);
    cudaGetSymbolAddress((void**)&klo, g_klo);
    cudaGetSymbolAddress((void**)&vhi, g_vhi);
    cudaGetSymbolAddress((void**)&vlo, g_vlo);
    cudaGetSymbolAddress((void**)&ohi, g_ohi);
    cudaGetSymbolAddress((void**)&olo, g_olo);
    cudaGetSymbolAddress((void**)&xhi, g_xhi);
    cudaGetSymbolAddress((void**)&xlo, g_xlo);
    cudaGetSymbolAddress((void**)&whi, g_whi);
    cudaGetSymbolAddress((void**)&wlo, g_wlo);

    cudaFuncSetAttribute(gemm_bf16_kernel, cudaFuncAttributeMaxDynamicSharedMemorySize, SM_TOTAL);
    cudaFuncSetAttribute(flash_mma_kernel, cudaFuncAttributeMaxDynamicSharedMemorySize, FSM_TOTAL);

    // prep: x -> bf16 hi/lo ; weights -> transposed bf16 hi/lo
    const int n4 = M_ * KDIM / 4;
    convert_split_kernel<<<(n4 + 255) / 256, 256>>>(x, xhi, xlo, n4);
    dim3 tGrid(KDIM / 32, HD_ / 32, 4);
    transpose_split_kernel<<<tGrid, dim3(32, 8)>>>(qm, km, vm, wm, whi, wlo);

    // fused QKV projection -> bf16 hi/lo splits in [B,H,T,DK] (q pre-scaled x8)
    dim3 qkvGrid(HD_ / 128, M_ / 128, 3);
    gemm_bf16_kernel<<<qkvGrid, 512, SM_TOTAL>>>(
        xhi, xlo, qhi, qlo, khi, klo, vhi, vlo, (float*)0, 0, 1);

    // tensor-core causal flash -> bf16 hi/lo O in [B,T,H*DK]
    dim3 flashGrid(T_ / 128, B_ * H_);
    flash_mma_kernel<<<flashGrid, 256, FSM_TOTAL>>>(
        qhi, qlo, khi, klo, vhi, vlo, ohi, olo);

    // output projection (fp32 out)
    dim3 oGrid(HD_ / 128, M_ / 128, 1);
    gemm_bf16_kernel<<<oGrid, 512, SM_TOTAL>>>(
        ohi, olo, (__nv_bfloat16*)0, (__nv_bfloat16*)0, (__nv_bfloat16*)0,
        (__nv_bfloat16*)0, (__nv_bfloat16*)0, (__nv_bfloat16*)0, out, 3, 0);
}